// round 3
// baseline (speedup 1.0000x reference)
#include <cuda_runtime.h>
#include <cstdint>

// ---------------------------------------------------------------------------
// Problem: GRU layer, B=32, T=2048, D=256, H=256, fp32, masked update.
// Plan:
//   Kernel 1: gx = x @ W_ih + b_ih  (big fp32 GEMM, f32x2 packed FMA)
//   Kernel 2: persistent recurrence. 16 clusters x 8 CTAs. Each cluster owns a
//             batch PAIR (packed as f32x2); each CTA owns 32 H-cols (96 gate
//             cols) with its W_hh slice dup-packed in REGISTERS. h exchanged
//             via DSMEM + barrier.cluster each step (double-buffered).
// Round 2 fix: mask is int32 (harness promotes bool -> int32), was read as u8.
// ---------------------------------------------------------------------------

#define B_  32
#define T_  2048
#define D_  256
#define H_  256
#define G3_ 768

// 192 MB scratch for gx (device-global arrays are the sanctioned scratch path)
__device__ float g_gx[(size_t)B_ * T_ * G3_];

// ---------------- f32x2 helpers ----------------
__device__ __forceinline__ unsigned long long pack2(float x, float y) {
    unsigned long long r;
    asm("mov.b64 %0, {%1, %2};" : "=l"(r) : "f"(x), "f"(y));
    return r;
}
__device__ __forceinline__ float2 unpack2(unsigned long long v) {
    float2 r;
    asm("mov.b64 {%0, %1}, %2;" : "=f"(r.x), "=f"(r.y) : "l"(v));
    return r;
}
__device__ __forceinline__ unsigned long long fma2(unsigned long long a,
                                                   unsigned long long b,
                                                   unsigned long long c) {
    unsigned long long d;
    asm("fma.rn.f32x2 %0, %1, %2, %3;" : "=l"(d) : "l"(a), "l"(b), "l"(c));
    return d;
}
__device__ __forceinline__ unsigned long long add2(unsigned long long a,
                                                   unsigned long long b) {
    unsigned long long d;
    asm("add.rn.f32x2 %0, %1, %2;" : "=l"(d) : "l"(a), "l"(b));
    return d;
}
__device__ __forceinline__ uint32_t smem_u32(const void* p) {
    uint32_t a;
    asm("{ .reg .u64 t; cvta.to.shared.u64 t, %1; cvt.u32.u64 %0, t; }"
        : "=r"(a) : "l"(p));
    return a;
}
__device__ __forceinline__ float sigmoidf_(float x) {
    return 1.0f / (1.0f + __expf(-x));
}

// ===========================================================================
// Kernel 1: gx[M=65536, N=768] = x[M, K=256] @ W_ih[K, N] + b_ih
// 128x128x16 tiles, 256 threads, 8x8 microtile via f32x2 packed FMA.
// ===========================================================================
#define BM 128
#define BN 128
#define BK 16

__global__ __launch_bounds__(256)
void gemm_gx_kernel(const float* __restrict__ A,     // x  [65536,256]
                    const float* __restrict__ Bw,    // W_ih [256,768]
                    const float* __restrict__ bias,  // b_ih [768]
                    float* __restrict__ C)           // gx [65536,768]
{
    const int N = G3_, K = D_;
    __shared__ __align__(16) float As[BK][BM];
    __shared__ __align__(16) float Bs[BK][BN];

    const int tid  = threadIdx.x;
    const int row0 = blockIdx.y * BM;
    const int col0 = blockIdx.x * BN;

    const int ty = tid >> 4, tx = tid & 15;
    const int m0 = ty * 8,  n0 = tx * 8;

    unsigned long long acc[8][4];
#pragma unroll
    for (int i = 0; i < 8; i++)
#pragma unroll
        for (int q = 0; q < 4; q++) acc[i][q] = 0ull;

    for (int k0 = 0; k0 < K; k0 += BK) {
        // Load A tile [BM][BK] -> transposed As[BK][BM]
#pragma unroll
        for (int it = 0; it < 2; it++) {
            int idx = tid + it * 256;         // 0..511 float4 slots
            int r   = idx >> 2;               // row in tile
            int kq  = idx & 3;                // which float4 along k
            float4 v = *(const float4*)&A[(size_t)(row0 + r) * K + k0 + kq * 4];
            As[kq * 4 + 0][r] = v.x;
            As[kq * 4 + 1][r] = v.y;
            As[kq * 4 + 2][r] = v.z;
            As[kq * 4 + 3][r] = v.w;
        }
        // Load B tile [BK][BN]
#pragma unroll
        for (int it = 0; it < 2; it++) {
            int idx = tid + it * 256;
            int kr  = idx >> 5;               // row (k) in tile
            int nq  = idx & 31;               // which float4 along n
            float4 v = *(const float4*)&Bw[(size_t)(k0 + kr) * N + col0 + nq * 4];
            *(float4*)&Bs[kr][nq * 4] = v;
        }
        __syncthreads();

#pragma unroll
        for (int k = 0; k < BK; k++) {
            float4 a03 = *(const float4*)&As[k][m0];
            float4 a47 = *(const float4*)&As[k][m0 + 4];
            float a[8] = {a03.x, a03.y, a03.z, a03.w, a47.x, a47.y, a47.z, a47.w};
            const ulonglong2* bp = (const ulonglong2*)&Bs[k][n0];
            ulonglong2 b01 = bp[0];
            ulonglong2 b23 = bp[1];
#pragma unroll
            for (int i = 0; i < 8; i++) {
                unsigned long long ad = pack2(a[i], a[i]);
                acc[i][0] = fma2(ad, b01.x, acc[i][0]);
                acc[i][1] = fma2(ad, b01.y, acc[i][1]);
                acc[i][2] = fma2(ad, b23.x, acc[i][2]);
                acc[i][3] = fma2(ad, b23.y, acc[i][3]);
            }
        }
        __syncthreads();
    }

    // bias + store
    float bl[8];
#pragma unroll
    for (int q = 0; q < 8; q++) bl[q] = bias[col0 + n0 + q];
#pragma unroll
    for (int i = 0; i < 8; i++) {
        float* cp = &C[(size_t)(row0 + m0 + i) * N + col0 + n0];
#pragma unroll
        for (int q = 0; q < 4; q++) {
            float2 v = unpack2(acc[i][q]);
            v.x += bl[2 * q];
            v.y += bl[2 * q + 1];
            *(float2*)&cp[2 * q] = v;
        }
    }
}

// ===========================================================================
// Kernel 2: recurrence. grid = 128 CTAs = 16 clusters x 8.
// Cluster cid owns batches (2*cid, 2*cid+1) packed as f32x2 lanes.
// CTA rank g owns H-cols [32g, 32g+32) -> 96 gate cols (r/z/n).
// 384 threads: j = tid % 96 (gate col), s = tid / 96 (k-quarter of 64).
// W_hh slice dup-packed in 64 b64 registers per thread. h in SMEM, double
// buffered, broadcast to peers via st.shared::cluster + barrier.cluster.
// ===========================================================================
__global__ void __cluster_dims__(8, 1, 1) __launch_bounds__(384, 1)
gru_recur_kernel(const float* __restrict__ gx,
                 const int* __restrict__ mask,      // bool promoted to int32
                 const float* __restrict__ h0,
                 const float* __restrict__ W_hh,
                 const float* __restrict__ b_hh,
                 float* __restrict__ out)
{
    __shared__ __align__(16) float2 sh_h[2][H_];        // [buf][k] = {b0,b1}
    __shared__ __align__(16) unsigned long long red[4][96];
    __shared__ __align__(16) unsigned long long ghsum[96];

    const int tid = threadIdx.x;
    const int j = tid % 96;          // gate column within CTA slice
    const int s = tid / 96;          // k-quarter (64 k's each)
    uint32_t rank;
    asm("mov.u32 %0, %%cluster_ctarank;" : "=r"(rank));
    const int cid = blockIdx.x >> 3;
    const int b0  = cid * 2;

    const int piece = j >> 5;        // 0=r,1=z,2=n
    const int cIn   = j & 31;
    const int gcol  = piece * 256 + (int)rank * 32 + cIn;
    const int k0    = s * 64;

    // ---- load W_hh slice into registers, dup-packed ----
    unsigned long long wp[64];
#pragma unroll
    for (int kk = 0; kk < 64; kk++) {
        float w = W_hh[(size_t)(k0 + kk) * G3_ + gcol];
        wp[kk] = pack2(w, w);
    }

    // ---- init h buffer 0 from h0 ----
    for (int k = tid; k < H_; k += 384)
        sh_h[0][k] = make_float2(h0[(size_t)b0 * H_ + k],
                                 h0[(size_t)(b0 + 1) * H_ + k]);
    __syncthreads();
    asm volatile("barrier.cluster.arrive.aligned;" ::: "memory");
    asm volatile("barrier.cluster.wait.aligned;" ::: "memory");

    // ---- epilogue-thread constants (threads 0..63: cc = col, bb = batch) ----
    float bh_r = 0.f, bh_z = 0.f, bh_n = 0.f;
    int cc = 0, bb = 0, hcol = 0;
    const float* gx_b = nullptr;
    const int* mask_b = nullptr;
    float* out_b = nullptr;
    if (tid < 64) {
        cc = tid & 31;
        bb = tid >> 5;
        hcol = (int)rank * 32 + cc;
        bh_r = b_hh[hcol];
        bh_z = b_hh[256 + hcol];
        bh_n = b_hh[512 + hcol];
        gx_b   = gx   + (size_t)(b0 + bb) * T_ * G3_;
        out_b  = out  + (size_t)(b0 + bb) * T_ * H_;
        mask_b = mask + (size_t)(b0 + bb) * T_;
    }

    const uint32_t sh_base = smem_u32(&sh_h[0][0]);
    int p = 0;

    for (int t = 0; t < T_; t++) {
        // prefetch gx + mask for this step (consumed after FMA phase)
        float gxr = 0.f, gxz = 0.f, gxn = 0.f;
        int m = 1;
        if (tid < 64) {
            const float* g = gx_b + (size_t)t * G3_ + hcol;
            gxr = g[0];
            gxz = g[256];
            gxn = g[512];
            m = mask_b[t];
        }

        // ---- FMA phase: gh partial for (col j, k-quarter s), both batches ----
        unsigned long long a0 = 0ull, a1 = 0ull;
        const ulonglong2* hp = (const ulonglong2*)&sh_h[p][k0];
#pragma unroll
        for (int kk = 0; kk < 32; kk++) {
            ulonglong2 hv = hp[kk];                     // h[k], h[k+1] pairs
            a0 = fma2(wp[2 * kk],     hv.x, a0);
            a1 = fma2(wp[2 * kk + 1], hv.y, a1);
        }
        red[s][j] = add2(a0, a1);
        __syncthreads();

        if (tid < 96) {
            unsigned long long gs = add2(add2(red[0][tid], red[1][tid]),
                                         add2(red[2][tid], red[3][tid]));
            ghsum[tid] = gs;
        }
        __syncthreads();

        if (tid < 64) {
            float2 vr = unpack2(ghsum[cc]);
            float2 vz = unpack2(ghsum[32 + cc]);
            float2 vn = unpack2(ghsum[64 + cc]);
            float ghr = bb ? vr.y : vr.x;
            float ghz = bb ? vz.y : vz.x;
            float ghn = bb ? vn.y : vn.x;
            float2 ho = sh_h[p][hcol];
            float hold = bb ? ho.y : ho.x;

            float r  = sigmoidf_(gxr + ghr + bh_r);
            float z  = sigmoidf_(gxz + ghz + bh_z);
            float hn = ghn + bh_n;                  // b_hh_n inside r*(...)
            float n  = tanhf(gxn + r * hn);
            float hnew = (1.0f - z) * n + z * hold;
            if (!m) hnew = hold;

            out_b[(size_t)t * H_ + hcol] = hnew;

            // broadcast h_new to all 8 cluster CTAs (incl. self), buffer 1-p
            uint32_t la = sh_base
                        + (uint32_t)(((1 - p) * H_ + hcol) * 8 + bb * 4);
#pragma unroll
            for (int rr = 0; rr < 8; rr++) {
                uint32_t ra;
                asm("mapa.shared::cluster.u32 %0, %1, %2;"
                    : "=r"(ra) : "r"(la), "r"((uint32_t)rr));
                asm volatile("st.shared::cluster.f32 [%0], %1;"
                             :: "r"(ra), "f"(hnew) : "memory");
            }
        }

        asm volatile("barrier.cluster.arrive.aligned;" ::: "memory");
        asm volatile("barrier.cluster.wait.aligned;" ::: "memory");
        p ^= 1;
    }
}

// ===========================================================================
// Launch
// ===========================================================================
extern "C" void kernel_launch(void* const* d_in, const int* in_sizes, int n_in,
                              void* d_out, int out_size)
{
    const float* x    = (const float*)d_in[0];
    const int*   mask = (const int*)d_in[1];
    const float* h0   = (const float*)d_in[2];
    const float* W_ih = (const float*)d_in[3];
    const float* W_hh = (const float*)d_in[4];
    const float* b_ih = (const float*)d_in[5];
    const float* b_hh = (const float*)d_in[6];
    float* out = (float*)d_out;

    float* gx;
    cudaGetSymbolAddress((void**)&gx, g_gx);

    dim3 g1(G3_ / BN, (B_ * T_) / BM);   // (6, 512)
    gemm_gx_kernel<<<g1, 256>>>(x, W_ih, b_ih, gx);

    gru_recur_kernel<<<128, 384>>>(gx, mask, h0, W_hh, b_hh, out);
}

// round 5
// speedup vs baseline: 1.0056x; 1.0056x over previous
#include <cuda_runtime.h>
#include <cstdint>

// ---------------------------------------------------------------------------
// GRU layer, B=32, T=2048, D=256, H=256, fp32, masked update.
//   Kernel 1: gx = x @ W_ih + b_ih via PORTABLE warp mma.sync tf32 (HMMA),
//             3-term 2xTF32 decomposition (tcgen05 unavailable: harness
//             targets sm_103 without the 'a' feature set).
//   Kernel 2: persistent cluster recurrence (unchanged from passing R3).
// ---------------------------------------------------------------------------

#define B_  32
#define T_  2048
#define D_  256
#define H_  256
#define G3_ 768

__device__ float g_gx[(size_t)B_ * T_ * G3_];

// ---------------- helpers ----------------
__device__ __forceinline__ unsigned long long pack2(float x, float y) {
    unsigned long long r;
    asm("mov.b64 %0, {%1, %2};" : "=l"(r) : "f"(x), "f"(y));
    return r;
}
__device__ __forceinline__ float2 unpack2(unsigned long long v) {
    float2 r;
    asm("mov.b64 {%0, %1}, %2;" : "=f"(r.x), "=f"(r.y) : "l"(v));
    return r;
}
__device__ __forceinline__ unsigned long long fma2(unsigned long long a,
                                                   unsigned long long b,
                                                   unsigned long long c) {
    unsigned long long d;
    asm("fma.rn.f32x2 %0, %1, %2, %3;" : "=l"(d) : "l"(a), "l"(b), "l"(c));
    return d;
}
__device__ __forceinline__ unsigned long long add2(unsigned long long a,
                                                   unsigned long long b) {
    unsigned long long d;
    asm("add.rn.f32x2 %0, %1, %2;" : "=l"(d) : "l"(a), "l"(b));
    return d;
}
__device__ __forceinline__ uint32_t smem_u32(const void* p) {
    uint32_t a;
    asm("{ .reg .u64 t; cvta.to.shared.u64 t, %1; cvt.u32.u64 %0, t; }"
        : "=r"(a) : "l"(p));
    return a;
}
__device__ __forceinline__ float sigmoidf_(float x) {
    return 1.0f / (1.0f + __expf(-x));
}
__device__ __forceinline__ uint32_t tf32_rna(float f) {
    uint32_t u;
    asm("cvt.rna.tf32.f32 %0, %1;" : "=r"(u) : "f"(f));
    return u;
}

// ===========================================================================
// Kernel 1: gx[65536,768] = x[65536,256] @ W_ih[256,768] + b_ih
// CTA 128x128 tile, BK=32, 256 threads = 8 warps in 2(M) x 4(N).
// Warp tile 64x32 via m16n8k8 tf32 mma.sync; 3-term 2xTF32.
// Dynamic smem: AH/AL [128][33], BH/BL [32][132] (u32 tf32 values).
// ===========================================================================
#define SM_AH 0
#define SM_AL 4224
#define SM_BH 8448
#define SM_BL 12672
#define SM_WORDS 16896   // 67584 bytes

__device__ __forceinline__ void mma_tf32(float c[4],
                                         uint32_t a0, uint32_t a1,
                                         uint32_t a2, uint32_t a3,
                                         uint32_t b0, uint32_t b1) {
    asm volatile(
        "mma.sync.aligned.m16n8k8.row.col.f32.tf32.tf32.f32 "
        "{%0,%1,%2,%3}, {%4,%5,%6,%7}, {%8,%9}, {%0,%1,%2,%3};"
        : "+f"(c[0]), "+f"(c[1]), "+f"(c[2]), "+f"(c[3])
        : "r"(a0), "r"(a1), "r"(a2), "r"(a3), "r"(b0), "r"(b1));
}

__global__ __launch_bounds__(256)
void gemm_gx_mma(const float* __restrict__ A,     // x  [65536,256]
                 const float* __restrict__ Bw,    // W_ih [256,768]
                 const float* __restrict__ bias,  // b_ih [768]
                 float* __restrict__ C)           // gx [65536,768]
{
    extern __shared__ uint32_t smu[];
    const int tid = threadIdx.x;
    const int wid = tid >> 5;
    const int lane = tid & 31;
    const int tg = lane >> 2;      // group id (0..7)
    const int tk = lane & 3;       // thread-in-group (0..3)

    const int warp_m = wid & 1;        // 0..1 -> 64 rows each
    const int warp_n = wid >> 1;       // 0..3 -> 32 cols each
    const int row0 = blockIdx.y * 128;
    const int col0 = blockIdx.x * 128;

    float acc[4][4][4];                // [fm][fn][reg]
#pragma unroll
    for (int i = 0; i < 4; i++)
#pragma unroll
        for (int j = 0; j < 4; j++)
#pragma unroll
            for (int q = 0; q < 4; q++) acc[i][j][q] = 0.0f;

    for (int c = 0; c < 8; c++) {
        const int k0 = c * 32;
        if (c) __syncthreads();     // protect smem reuse

        // ---- A tile [128 x 32] -> AH/AL, stride 33 ----
#pragma unroll
        for (int it = 0; it < 4; it++) {
            int idx = tid + it * 256;          // 0..1023 float4 slots
            int r = idx >> 3;
            int q = (idx & 7) * 4;
            float4 v = *(const float4*)&A[(size_t)(row0 + r) * D_ + k0 + q];
            uint32_t base = r * 33 + q;
            uint32_t h;
            h = tf32_rna(v.x); smu[SM_AH + base + 0] = h;
            smu[SM_AL + base + 0] = tf32_rna(v.x - __uint_as_float(h));
            h = tf32_rna(v.y); smu[SM_AH + base + 1] = h;
            smu[SM_AL + base + 1] = tf32_rna(v.y - __uint_as_float(h));
            h = tf32_rna(v.z); smu[SM_AH + base + 2] = h;
            smu[SM_AL + base + 2] = tf32_rna(v.z - __uint_as_float(h));
            h = tf32_rna(v.w); smu[SM_AH + base + 3] = h;
            smu[SM_AL + base + 3] = tf32_rna(v.w - __uint_as_float(h));
        }

        // ---- B tile [32 x 128] -> BH/BL, stride 132, vectorized ----
#pragma unroll
        for (int it = 0; it < 4; it++) {
            int idx = tid + it * 256;          // 0..1023 float4 slots
            int kk = idx >> 5;
            int n4 = (idx & 31) * 4;
            float4 v = *(const float4*)&Bw[(size_t)(k0 + kk) * G3_ + col0 + n4];
            uint4 hi, lo;
            hi.x = tf32_rna(v.x); lo.x = tf32_rna(v.x - __uint_as_float(hi.x));
            hi.y = tf32_rna(v.y); lo.y = tf32_rna(v.y - __uint_as_float(hi.y));
            hi.z = tf32_rna(v.z); lo.z = tf32_rna(v.z - __uint_as_float(hi.z));
            hi.w = tf32_rna(v.w); lo.w = tf32_rna(v.w - __uint_as_float(hi.w));
            uint32_t base = kk * 132 + n4;
            *(uint4*)&smu[SM_BH + base] = hi;
            *(uint4*)&smu[SM_BL + base] = lo;
        }
        __syncthreads();

        // ---- 4 ksteps of 8 ----
#pragma unroll
        for (int ks = 0; ks < 4; ks++) {
            const int kb = ks * 8;
            // B fragments (preload all 4 n-blocks)
            uint32_t bh[4][2], bl[4][2];
#pragma unroll
            for (int fn = 0; fn < 4; fn++) {
                int n = warp_n * 32 + fn * 8 + tg;
                bh[fn][0] = smu[SM_BH + (kb + tk) * 132 + n];
                bh[fn][1] = smu[SM_BH + (kb + tk + 4) * 132 + n];
                bl[fn][0] = smu[SM_BL + (kb + tk) * 132 + n];
                bl[fn][1] = smu[SM_BL + (kb + tk + 4) * 132 + n];
            }
#pragma unroll
            for (int fm = 0; fm < 4; fm++) {
                int r = warp_m * 64 + fm * 16 + tg;
                uint32_t ah0 = smu[SM_AH + r * 33 + kb + tk];
                uint32_t ah1 = smu[SM_AH + (r + 8) * 33 + kb + tk];
                uint32_t ah2 = smu[SM_AH + r * 33 + kb + tk + 4];
                uint32_t ah3 = smu[SM_AH + (r + 8) * 33 + kb + tk + 4];
                uint32_t al0 = smu[SM_AL + r * 33 + kb + tk];
                uint32_t al1 = smu[SM_AL + (r + 8) * 33 + kb + tk];
                uint32_t al2 = smu[SM_AL + r * 33 + kb + tk + 4];
                uint32_t al3 = smu[SM_AL + (r + 8) * 33 + kb + tk + 4];
#pragma unroll
                for (int fn = 0; fn < 4; fn++) {
                    mma_tf32(acc[fm][fn], ah0, ah1, ah2, ah3,
                             bh[fn][0], bh[fn][1]);
                    mma_tf32(acc[fm][fn], al0, al1, al2, al3,
                             bh[fn][0], bh[fn][1]);
                    mma_tf32(acc[fm][fn], ah0, ah1, ah2, ah3,
                             bl[fn][0], bl[fn][1]);
                }
            }
        }
    }

    // ---- epilogue: bias + store ----
#pragma unroll
    for (int fm = 0; fm < 4; fm++) {
        int r1 = row0 + warp_m * 64 + fm * 16 + tg;
        int r2 = r1 + 8;
#pragma unroll
        for (int fn = 0; fn < 4; fn++) {
            int col = col0 + warp_n * 32 + fn * 8 + 2 * tk;
            float b0 = bias[col], b1 = bias[col + 1];
            float2 v0 = make_float2(acc[fm][fn][0] + b0, acc[fm][fn][1] + b1);
            float2 v1 = make_float2(acc[fm][fn][2] + b0, acc[fm][fn][3] + b1);
            *(float2*)&C[(size_t)r1 * G3_ + col] = v0;
            *(float2*)&C[(size_t)r2 * G3_ + col] = v1;
        }
    }
}

// ===========================================================================
// Kernel 2: recurrence (unchanged from passing Round-3 version).
// ===========================================================================
__global__ void __cluster_dims__(8, 1, 1) __launch_bounds__(384, 1)
gru_recur_kernel(const float* __restrict__ gx,
                 const int* __restrict__ mask,
                 const float* __restrict__ h0,
                 const float* __restrict__ W_hh,
                 const float* __restrict__ b_hh,
                 float* __restrict__ out)
{
    __shared__ __align__(16) float2 sh_h[2][H_];
    __shared__ __align__(16) unsigned long long red[4][96];
    __shared__ __align__(16) unsigned long long ghsum[96];

    const int tid = threadIdx.x;
    const int j = tid % 96;
    const int s = tid / 96;
    uint32_t rank;
    asm("mov.u32 %0, %%cluster_ctarank;" : "=r"(rank));
    const int cid = blockIdx.x >> 3;
    const int b0  = cid * 2;

    const int piece = j >> 5;
    const int cIn   = j & 31;
    const int gcol  = piece * 256 + (int)rank * 32 + cIn;
    const int k0    = s * 64;

    unsigned long long wp[64];
#pragma unroll
    for (int kk = 0; kk < 64; kk++) {
        float w = W_hh[(size_t)(k0 + kk) * G3_ + gcol];
        wp[kk] = pack2(w, w);
    }

    for (int k = tid; k < H_; k += 384)
        sh_h[0][k] = make_float2(h0[(size_t)b0 * H_ + k],
                                 h0[(size_t)(b0 + 1) * H_ + k]);
    __syncthreads();
    asm volatile("barrier.cluster.arrive.aligned;" ::: "memory");
    asm volatile("barrier.cluster.wait.aligned;" ::: "memory");

    float bh_r = 0.f, bh_z = 0.f, bh_n = 0.f;
    int cc = 0, bb = 0, hcol = 0;
    const float* gx_b = nullptr;
    const int* mask_b = nullptr;
    float* out_b = nullptr;
    if (tid < 64) {
        cc = tid & 31;
        bb = tid >> 5;
        hcol = (int)rank * 32 + cc;
        bh_r = b_hh[hcol];
        bh_z = b_hh[256 + hcol];
        bh_n = b_hh[512 + hcol];
        gx_b   = gx   + (size_t)(b0 + bb) * T_ * G3_;
        out_b  = out  + (size_t)(b0 + bb) * T_ * H_;
        mask_b = mask + (size_t)(b0 + bb) * T_;
    }

    const uint32_t sh_base = smem_u32(&sh_h[0][0]);
    int p = 0;

    for (int t = 0; t < T_; t++) {
        float gxr = 0.f, gxz = 0.f, gxn = 0.f;
        int m = 1;
        if (tid < 64) {
            const float* g = gx_b + (size_t)t * G3_ + hcol;
            gxr = g[0];
            gxz = g[256];
            gxn = g[512];
            m = mask_b[t];
        }

        unsigned long long a0 = 0ull, a1 = 0ull;
        const ulonglong2* hp = (const ulonglong2*)&sh_h[p][k0];
#pragma unroll
        for (int kk = 0; kk < 32; kk++) {
            ulonglong2 hv = hp[kk];
            a0 = fma2(wp[2 * kk],     hv.x, a0);
            a1 = fma2(wp[2 * kk + 1], hv.y, a1);
        }
        red[s][j] = add2(a0, a1);
        __syncthreads();

        if (tid < 96) {
            unsigned long long gs = add2(add2(red[0][tid], red[1][tid]),
                                         add2(red[2][tid], red[3][tid]));
            ghsum[tid] = gs;
        }
        __syncthreads();

        if (tid < 64) {
            float2 vr = unpack2(ghsum[cc]);
            float2 vz = unpack2(ghsum[32 + cc]);
            float2 vn = unpack2(ghsum[64 + cc]);
            float ghr = bb ? vr.y : vr.x;
            float ghz = bb ? vz.y : vz.x;
            float ghn = bb ? vn.y : vn.x;
            float2 ho = sh_h[p][hcol];
            float hold = bb ? ho.y : ho.x;

            float r  = sigmoidf_(gxr + ghr + bh_r);
            float z  = sigmoidf_(gxz + ghz + bh_z);
            float hn = ghn + bh_n;
            float n  = tanhf(gxn + r * hn);
            float hnew = (1.0f - z) * n + z * hold;
            if (!m) hnew = hold;

            out_b[(size_t)t * H_ + hcol] = hnew;

            uint32_t la = sh_base
                        + (uint32_t)(((1 - p) * H_ + hcol) * 8 + bb * 4);
#pragma unroll
            for (int rr = 0; rr < 8; rr++) {
                uint32_t ra;
                asm("mapa.shared::cluster.u32 %0, %1, %2;"
                    : "=r"(ra) : "r"(la), "r"((uint32_t)rr));
                asm volatile("st.shared::cluster.f32 [%0], %1;"
                             :: "r"(ra), "f"(hnew) : "memory");
            }
        }

        asm volatile("barrier.cluster.arrive.aligned;" ::: "memory");
        asm volatile("barrier.cluster.wait.aligned;" ::: "memory");
        p ^= 1;
    }
}

// ===========================================================================
// Launch
// ===========================================================================
extern "C" void kernel_launch(void* const* d_in, const int* in_sizes, int n_in,
                              void* d_out, int out_size)
{
    const float* x    = (const float*)d_in[0];
    const int*   mask = (const int*)d_in[1];
    const float* h0   = (const float*)d_in[2];
    const float* W_ih = (const float*)d_in[3];
    const float* W_hh = (const float*)d_in[4];
    const float* b_ih = (const float*)d_in[5];
    const float* b_hh = (const float*)d_in[6];
    float* out = (float*)d_out;

    float* gx;
    cudaGetSymbolAddress((void**)&gx, g_gx);

    cudaFuncSetAttribute(gemm_gx_mma,
                         cudaFuncAttributeMaxDynamicSharedMemorySize,
                         SM_WORDS * 4);

    dim3 g1(G3_ / 128, (B_ * T_) / 128);   // (6, 512)
    gemm_gx_mma<<<g1, 256, SM_WORDS * 4>>>(x, W_ih, b_ih, gx);

    gru_recur_kernel<<<128, 384>>>(gx, mask, h0, W_hh, b_hh, out);
}